// round 4
// baseline (speedup 1.0000x reference)
#include <cuda_runtime.h>
#include <cuda_bf16.h>

// B=16, C=128, H=W=224, KS=3, STRIDE=2, ALPHA=16 -> h[z] = -(z/t)^16; Ho=Wo=111.
#define B_  16
#define C_  128
#define H_  224
#define W_  224
#define HO_ 111
#define WO_ 111
#define TR  8                       // output rows per block

__global__ __launch_bounds__(128)
void lfp_kernel(const float* __restrict__ f,
                const float* __restrict__ t,
                float* __restrict__ out)
{
    const int tid    = threadIdx.x;
    const bool lane31 = ((tid & 31) == 31);
    const int j  = tid;                        // output column (0..110 valid)
    const int jj = (j < WO_) ? j : WO_;        // clamp to 111: cols 222,223 still in-bounds
    const int bc = blockIdx.y;                 // b*C + c
    const int c  = bc & (C_ - 1);

    // h0 = 0, h1 = -(1/t)^16, h2 = -(2/t)^16
    const float inv = 1.0f / __ldg(t + c);
    const float x2  = inv * inv;
    const float x4  = x2 * x2;
    const float x8  = x4 * x4;
    const float x16 = x8 * x8;
    const float h1  = -x16;
    const float h2  = -65536.0f * x16;

    const float* __restrict__ fb = f + (size_t)bc * (H_ * W_);
    float* __restrict__ ob = out + (size_t)bc * (HO_ * WO_);

    const int i0   = blockIdx.x * TR;
    int       iend = i0 + TR;
    if (iend > HO_) iend = HO_;

    // Per input row r: center = f[r,2j+1], edge = max(f[r,2j], f[r,2j+2]).
    // Dense float2 load gives cols (2j, 2j+1); col 2j+2 comes from lane+1's .x
    // via shuffle (lane 31 of each warp does a predicated scalar load).
    #define LOADROW(r, cc, ee)                                                 \
    {                                                                          \
        const float2 a = ((const float2*)(fb + (size_t)(r) * W_))[jj];         \
        float d = __shfl_down_sync(0xffffffffu, a.x, 1);                       \
        if (lane31) d = fb[(size_t)(r) * W_ + 2 * jj + 2];                     \
        (cc) = a.y; (ee) = fmaxf(a.x, d);                                      \
    }

    float c0, e0;
    LOADROW(2 * i0, c0, e0);

    #pragma unroll
    for (int ii = 0; ii < TR; ++ii) {
        const int i = i0 + ii;
        if (i >= iend) break;                  // uniform per block: warp-safe
        float c1, e1, c2, e2;
        LOADROW(2 * i + 1, c1, e1);
        LOADROW(2 * i + 2, c2, e2);

        float v = fmaxf(fmaxf(c1, e1 + h1),
                        fmaxf(fmaxf(c0, c2) + h1, fmaxf(e0, e2) + h2));
        if (j < WO_) ob[(size_t)i * WO_ + j] = v;

        c0 = c2; e0 = e2;
    }
    #undef LOADROW
}

extern "C" void kernel_launch(void* const* d_in, const int* in_sizes, int n_in,
                              void* d_out, int out_size)
{
    const float* f = (const float*)d_in[0];
    const float* t = (const float*)d_in[1];
    float* out = (float*)d_out;

    dim3 block(128, 1, 1);
    dim3 grid((HO_ + TR - 1) / TR, B_ * C_, 1);
    lfp_kernel<<<grid, block>>>(f, t, out);
}

// round 6
// speedup vs baseline: 1.3671x; 1.3671x over previous
#include <cuda_runtime.h>
#include <cuda_bf16.h>

// B=16, C=128, H=W=224, KS=3, STRIDE=2, ALPHA=16 -> h[z] = -(z/t)^16; Ho=Wo=111.
#define B_  16
#define C_  128
#define H_  224
#define W_  224
#define HO_ 111
#define WO_ 111
#define TR  4                        // output rows per thread
#define NROWS (2*TR + 1)             // 9 input rows

__global__ __launch_bounds__(64)
void lfp_kernel(const float* __restrict__ f,
                const float* __restrict__ t,
                float* __restrict__ out)
{
    const int tid = threadIdx.x;                 // 0..63
    const int k   = (tid < 56) ? tid : 55;       // float4 index within row (clamped)
    const int bc  = blockIdx.y;                  // b*C + c
    const int c   = bc & (C_ - 1);

    // h0 = 0, h1 = -(1/t)^16, h2 = -(2/t)^16
    const float inv = 1.0f / __ldg(t + c);
    const float x2  = inv * inv;
    const float x4  = x2 * x2;
    const float x8  = x4 * x4;
    const float x16 = x8 * x8;
    const float h1  = -x16;
    const float h2  = -65536.0f * x16;

    const float* __restrict__ fb = f + (size_t)bc * (H_ * W_);
    float* __restrict__ ob = out + (size_t)bc * (HO_ * WO_);

    const int i0 = blockIdx.x * TR;              // first output row (0,4,...,108)
    const int r0 = 2 * i0;                       // first input row

    // ---- Phase 1: issue all 9 row loads upfront (max MLP) ----
    float4 A[NROWS];
    float  X[NROWS];                             // col 128 patch for warp0 lane31
    const bool patch = (tid == 31);
    #pragma unroll
    for (int r = 0; r < NROWS; ++r) {
        int gr = r0 + r;
        if (gr > H_ - 1) gr = H_ - 1;            // clamp; clamped rows never used
        const float* row = fb + (size_t)gr * W_;
        A[r] = ((const float4*)row)[k];
        if (patch) X[r] = row[128];              // warp0 lane31 neighbor col
    }

    // ---- Phase 2: per-row center/edge values for the 2 owned output columns ----
    // j = 2k:   cols (4k, 4k+1, 4k+2)       -> ca = A.y, ea = max(A.x, A.z)
    // j = 2k+1: cols (4k+2, 4k+3, 4k+4)     -> cb = A.w, eb = max(A.z, nx)
    float ca[NROWS], ea[NROWS], cb[NROWS], eb[NROWS];
    #pragma unroll
    for (int r = 0; r < NROWS; ++r) {
        float nx = __shfl_down_sync(0xffffffffu, A[r].x, 1);
        if (patch) nx = X[r];
        ca[r] = A[r].y;
        ea[r] = fmaxf(A[r].x, A[r].z);
        cb[r] = A[r].w;
        eb[r] = fmaxf(A[r].z, nx);
    }

    // ---- Phase 3: 4 output rows x 2 columns ----
    const int ja = 2 * k;                        // 0..110
    const int jb = ja + 1;                       // 1..111 (111 predicated off)
    const bool wa = (tid < 56);
    const bool wb = wa && (jb < WO_);

    #pragma unroll
    for (int ii = 0; ii < TR; ++ii) {
        const int i = i0 + ii;
        if (i >= HO_) break;
        const int rt = 2 * ii, rm = rt + 1, rb = rt + 2;

        float va = fmaxf(fmaxf(ca[rm], ea[rm] + h1),
                         fmaxf(fmaxf(ca[rt], ca[rb]) + h1,
                               fmaxf(ea[rt], ea[rb]) + h2));
        float vb = fmaxf(fmaxf(cb[rm], eb[rm] + h1),
                         fmaxf(fmaxf(cb[rt], cb[rb]) + h1,
                               fmaxf(eb[rt], eb[rb]) + h2));

        float* orow = ob + (size_t)i * WO_;
        if (wa) orow[ja] = va;
        if (wb) orow[jb] = vb;
    }
}

extern "C" void kernel_launch(void* const* d_in, const int* in_sizes, int n_in,
                              void* d_out, int out_size)
{
    const float* f = (const float*)d_in[0];
    const float* t = (const float*)d_in[1];
    float* out = (float*)d_out;

    dim3 block(64, 1, 1);
    dim3 grid((HO_ + TR - 1) / TR, B_ * C_, 1);   // 28 x 2048
    lfp_kernel<<<grid, block>>>(f, t, out);
}